// round 6
// baseline (speedup 1.0000x reference)
#include <cuda_runtime.h>
#include <cstdint>

#define B_ 16
#define N_ 577
#define H_ 12
#define D_ 64
#define C_ 768
#define BH_ 192
#define M_ 9232
#define KTS 640       // vT row stride (zero-padded cols 577..639)
#define SCALE_ 0.125f

// ---------------- device scratch (no cudaMalloc allowed) ----------------
__device__ float g_q[BH_ * N_ * D_];                 // (bh, n, d)
__device__ float g_k[BH_ * N_ * D_];                 // (bh, n, d)
__device__ float g_vT[BH_ * D_ * KTS];               // (bh, d, m) zero-padded
__device__ float g_pxy[BH_ * N_ * 104];              // px[0:52), py[52:104)
__device__ float g_ao[M_ * C_];                      // attention out (b*n, c)

// ---------------- tf32 helpers (base sm_103 target) ----------------
__device__ __forceinline__ uint32_t f2tf(float f) {
  uint32_t r;
  asm("cvt.rna.tf32.f32 %0, %1;" : "=r"(r) : "f"(f));
  return r;
}
__device__ __forceinline__ void mma16n8k8(float* d, const uint32_t* a,
                                          uint32_t b0, uint32_t b1) {
  asm volatile(
      "mma.sync.aligned.m16n8k8.row.col.f32.tf32.tf32.f32 "
      "{%0,%1,%2,%3}, {%4,%5,%6,%7}, {%8,%9}, {%0,%1,%2,%3};"
      : "+f"(d[0]), "+f"(d[1]), "+f"(d[2]), "+f"(d[3])
      : "r"(a[0]), "r"(a[1]), "r"(a[2]), "r"(a[3]), "r"(b0), "r"(b1));
}

// ======== tf32 mma.sync GEMM: C[m,c] = sum_k A[m,k] * W[c,k] ========
// MODE 0: A = x, scatter-store q/k natural + vT transposed
// MODE 1: A = g_ao, row-major store into out
template <int MODE>
__global__ __launch_bounds__(256)
void mma_gemm_kernel(const float* __restrict__ Ain, const float* __restrict__ W,
                     float* __restrict__ out) {
  __shared__ uint32_t As[128][36];
  __shared__ uint32_t Bs[128][36];
  const float* A = (MODE == 0) ? Ain : (const float*)g_ao;
  const int row0 = blockIdx.y * 128, col0 = blockIdx.x * 128;
  const int tid = threadIdx.x, lane = tid & 31, wid = tid >> 5;
  const int warpM = wid & 3, warpN = wid >> 2;
  const int g = lane >> 2, tg = lane & 3;

  float acc[16][4];
#pragma unroll
  for (int i = 0; i < 16; i++)
#pragma unroll
    for (int j = 0; j < 4; j++) acc[i][j] = 0.f;

  const int lr = tid >> 1;
  const int lkq = (tid & 1) * 16;
  const bool aval = (row0 + lr) < M_;
  const float* ap = A + (size_t)(row0 + lr) * C_ + lkq;
  const float* bp = W + (size_t)(col0 + lr) * C_ + lkq;

  for (int k0 = 0; k0 < C_; k0 += 32) {
    __syncthreads();
#pragma unroll
    for (int i = 0; i < 4; i++) {
      float4 va = aval ? *(const float4*)(ap + k0 + i * 4)
                       : make_float4(0.f, 0.f, 0.f, 0.f);
      float4 vb = *(const float4*)(bp + k0 + i * 4);
      *(uint4*)&As[lr][lkq + i * 4] =
          make_uint4(f2tf(va.x), f2tf(va.y), f2tf(va.z), f2tf(va.w));
      *(uint4*)&Bs[lr][lkq + i * 4] =
          make_uint4(f2tf(vb.x), f2tf(vb.y), f2tf(vb.z), f2tf(vb.w));
    }
    __syncthreads();
#pragma unroll
    for (int s = 0; s < 4; s++) {
      const int kk = s * 8;
      uint32_t a[2][4];
#pragma unroll
      for (int mt = 0; mt < 2; mt++) {
        const int r = warpM * 32 + mt * 16;
        a[mt][0] = As[r + g][kk + tg];
        a[mt][1] = As[r + g + 8][kk + tg];
        a[mt][2] = As[r + g][kk + tg + 4];
        a[mt][3] = As[r + g + 8][kk + tg + 4];
      }
#pragma unroll
      for (int nt = 0; nt < 8; nt++) {
        const int c = warpN * 64 + nt * 8;
        uint32_t b0 = Bs[c + g][kk + tg];
        uint32_t b1 = Bs[c + g][kk + tg + 4];
        mma16n8k8(acc[nt], a[0], b0, b1);
        mma16n8k8(acc[8 + nt], a[1], b0, b1);
      }
    }
  }

  if (MODE == 1) {
#pragma unroll
    for (int mt = 0; mt < 2; mt++)
#pragma unroll
      for (int half = 0; half < 2; half++) {
        const int m = row0 + warpM * 32 + mt * 16 + g + half * 8;
        if (m >= M_) continue;
        float* dst = out + (size_t)m * C_ + col0 + warpN * 64 + 2 * tg;
#pragma unroll
        for (int nt = 0; nt < 8; nt++)
          *(float2*)(dst + nt * 8) = make_float2(acc[mt * 8 + nt][half * 2],
                                                 acc[mt * 8 + nt][half * 2 + 1]);
      }
  } else {
    const int cg = col0 + warpN * 64;   // multiple of 64 -> one head per warp
    const int which = cg / C_;          // 0=q 1=k 2=v
    const int h = (cg % C_) / D_;
#pragma unroll
    for (int mt = 0; mt < 2; mt++)
#pragma unroll
      for (int half = 0; half < 2; half++) {
        const int m = row0 + warpM * 32 + mt * 16 + g + half * 8;
        if (m >= M_) continue;
        const int b = m / N_, n = m % N_;
        const int bh = b * H_ + h;
        if (which == 2) {
          const size_t base = (size_t)bh * D_ * KTS + n;
          const int d0 = 2 * tg;
#pragma unroll
          for (int nt = 0; nt < 8; nt++) {
            g_vT[base + (size_t)(d0 + nt * 8) * KTS] = acc[mt * 8 + nt][half * 2];
            g_vT[base + (size_t)(d0 + nt * 8 + 1) * KTS] =
                acc[mt * 8 + nt][half * 2 + 1];
          }
        } else {
          float* dst = (which == 0 ? g_q : g_k) + ((size_t)bh * N_ + n) * D_ + 2 * tg;
#pragma unroll
          for (int nt = 0; nt < 8; nt++)
            *(float2*)(dst + nt * 8) =
                make_float2(acc[mt * 8 + nt][half * 2],
                            acc[mt * 8 + nt][half * 2 + 1]);
        }
      }
  }
}

// ---------------- px/py projection ----------------
__global__ __launch_bounds__(256)
void pxpy_kernel(const float* __restrict__ qxe, const float* __restrict__ qye) {
  __shared__ float qs[64][65];
  __shared__ float ex[50][33];
  __shared__ float ey[50][33];
  const int bh = blockIdx.y;
  const int row0 = blockIdx.x * 64;
  const int tid = threadIdx.x;
  for (int f = tid; f < 64 * 16; f += 256) {
    int r = f >> 4, c4 = (f & 15) << 2;
    int n = row0 + r;
    float4 v = (n < N_) ? *(const float4*)(g_q + ((size_t)bh * N_ + n) * D_ + c4)
                        : make_float4(0.f, 0.f, 0.f, 0.f);
    qs[r][c4 + 0] = v.x; qs[r][c4 + 1] = v.y;
    qs[r][c4 + 2] = v.z; qs[r][c4 + 3] = v.w;
  }
  for (int f = tid; f < 1600; f += 256) {
    ex[f >> 5][f & 31] = qxe[f];
    ey[f >> 5][f & 31] = qye[f];
  }
  __syncthreads();
  for (int idx = tid; idx < 64 * 50; idx += 256) {
    int r = idx / 50, t = idx % 50;
    float ax = 0.f, ay = 0.f;
#pragma unroll
    for (int d = 0; d < 32; d++) {
      ax += qs[r][d] * ex[t][d];
      ay += qs[r][32 + d] * ey[t][d];
    }
    int n = row0 + r;
    if (n < N_) {
      float* p = g_pxy + ((size_t)bh * N_ + n) * 104;
      p[t] = ax;
      p[52 + t] = ay;
    }
  }
}

// ============ fused attention: scores + softmax + bins + AV + bias ============
// CTA: 64 query rows of one bh, 512 threads (16 warps).
// smem: S[64][620] fp32 (158720 B) then phase-aliased region Y:
//   scores: Ks[128][68] uint (0..34816)
//   av:     Vs[64][36] (0..9216), bxs[64][60] (9216..), bys (24576..),
//           exs[32][60] (39936..), eys (47616..), invs[64] f32 (55296..)
#define FA_SSTR 620
#define FA_SMEM 214272

__global__ __launch_bounds__(512)
void fused_attn_kernel(const float* __restrict__ vxe, const float* __restrict__ vye) {
  extern __shared__ char fsm[];
  float* S = (float*)fsm;
  char* Y = fsm + 64 * FA_SSTR * 4;
  uint32_t* Ks = (uint32_t*)Y;                 // [128][68] (scores phase)
  uint32_t* Vs = (uint32_t*)Y;                 // [64][36]  (AV phase)
  uint32_t* bxs = (uint32_t*)(Y + 9216);       // [64][60]
  uint32_t* bys = (uint32_t*)(Y + 24576);      // [64][60]
  uint32_t* exs = (uint32_t*)(Y + 39936);      // [32][60]
  uint32_t* eys = (uint32_t*)(Y + 47616);      // [32][60]
  float* invs = (float*)(Y + 55296);           // [64]

  const int bh = blockIdx.y, row0 = blockIdx.x * 64;
  const int tid = threadIdx.x, lane = tid & 31, wid = tid >> 5;
  const int warpM = wid & 3, warpN = wid >> 2;
  const int g = lane >> 2, tg = lane & 3;

  // ---- stage value embeddings (region disjoint from Ks) ----
  for (int f = tid; f < 32 * 60; f += 512) {
    int c = f / 60, t = f % 60;
    exs[f] = (t < 50) ? f2tf(vxe[t * 32 + c]) : 0u;
    eys[f] = (t < 50) ? f2tf(vye[t * 32 + c]) : 0u;
  }

  // ---- q fragments in registers (once) ----
  uint32_t qf[8][4];
  {
    const int n0 = row0 + warpM * 16 + g, n1 = n0 + 8;
    const float* q0 = g_q + ((size_t)bh * N_ + n0) * D_;
    const float* q1 = g_q + ((size_t)bh * N_ + n1) * D_;
    const bool v0 = n0 < N_, v1 = n1 < N_;
#pragma unroll
    for (int s = 0; s < 8; s++) {
      const int k = s * 8 + tg;
      qf[s][0] = v0 ? f2tf(q0[k]) : 0u;
      qf[s][1] = v1 ? f2tf(q1[k]) : 0u;
      qf[s][2] = v0 ? f2tf(q0[k + 4]) : 0u;
      qf[s][3] = v1 ? f2tf(q1[k + 4]) : 0u;
    }
  }

  // ---- scores: S[r][m] = q·k ----
  for (int ct = 0; ct < 5; ct++) {
    const int col0 = ct * 128;
    __syncthreads();
    for (int f = tid; f < 2048; f += 512) {
      int r = f >> 4, c4 = (f & 15) << 2;
      int kn = col0 + r;
      float4 v = (kn < N_) ? *(const float4*)(g_k + ((size_t)bh * N_ + kn) * D_ + c4)
                           : make_float4(0.f, 0.f, 0.f, 0.f);
      *(uint4*)&Ks[r * 68 + c4] =
          make_uint4(f2tf(v.x), f2tf(v.y), f2tf(v.z), f2tf(v.w));
    }
    __syncthreads();
    float acc[4][4];
#pragma unroll
    for (int i = 0; i < 4; i++)
#pragma unroll
      for (int j = 0; j < 4; j++) acc[i][j] = 0.f;
#pragma unroll
    for (int s = 0; s < 8; s++) {
      const int kk = s * 8;
#pragma unroll
      for (int nt = 0; nt < 4; nt++) {
        uint32_t b0 = Ks[(warpN * 32 + nt * 8 + g) * 68 + kk + tg];
        uint32_t b1 = Ks[(warpN * 32 + nt * 8 + g) * 68 + kk + tg + 4];
        mma16n8k8(acc[nt], qf[s], b0, b1);
      }
    }
#pragma unroll
    for (int nt = 0; nt < 4; nt++) {
      const int col = col0 + warpN * 32 + nt * 8 + 2 * tg;
      if (col < 608) {
        float* s0 = S + (size_t)(warpM * 16 + g) * FA_SSTR + col;
        float* s1 = S + (size_t)(warpM * 16 + g + 8) * FA_SSTR + col;
        s0[0] = acc[nt][0]; s0[1] = acc[nt][1];
        s1[0] = acc[nt][2]; s1[1] = acc[nt][3];
      }
    }
  }
  __syncthreads();

  // ---- softmax + bias + analytic binning (per warp: 4 rows) ----
  for (int q = 0; q < 4; q++) {
    const int r = wid * 4 + q;
    const int n = row0 + r;
    float* Srow = S + (size_t)r * FA_SSTR;
    if (n < N_) {
      const float* pxy = g_pxy + ((size_t)bh * N_ + n) * 104;
      const bool cls = (n == 0);
      const int xcol = cls ? 0 : (n - 1) % 24;
      const int yrow = cls ? 0 : (n - 1) / 24;
      float pxl = 0.f, pyl = 0.f;
      if (lane < 24) {
        pxl = cls ? pxy[0] : pxy[25 + lane - xcol];
        pyl = cls ? pxy[52] : pxy[52 + 25 + lane - yrow];
      }
      const float l0 = (Srow[0] + pxy[0] + pxy[52]) * SCALE_;
      float mx = l0;
      float lg[24];
#pragma unroll
      for (int k = 0; k < 24; k++) {
        float pyk = __shfl_sync(0xffffffffu, pyl, k);
        float s = -1e30f;
        if (lane < 24) s = (Srow[1 + 24 * k + lane] + pxl + pyk) * SCALE_;
        lg[k] = s;
        mx = fmaxf(mx, s);
      }
#pragma unroll
      for (int o = 16; o; o >>= 1) mx = fmaxf(mx, __shfl_xor_sync(0xffffffffu, mx, o));

      float colsum = 0.f, total = 0.f, binyreg = 0.f;
      const float e0 = __expf(l0 - mx);
#pragma unroll
      for (int k = 0; k < 24; k++) {
        float e = 0.f;
        if (lane < 24) {
          e = __expf(lg[k] - mx);
          Srow[1 + 24 * k + lane] = e;
        }
        colsum += e;
        float rs = e;
#pragma unroll
        for (int o = 16; o; o >>= 1) rs += __shfl_xor_sync(0xffffffffu, rs, o);
        total += rs;
        if (lane == k) binyreg = rs;
      }
      if (lane == 0) Srow[0] = e0;
      Srow[577 + lane] = 0.f;  // zero-pad cols 577..608
      total += e0;
      if (lane == 0) invs[r] = 1.f / total;

#pragma unroll
      for (int t0 = 0; t0 < 64; t0 += 32) {
        const int t = t0 + lane;
        float vx, vy;
        if (cls) {
          vx = (t == 0) ? total : 0.f;
          vy = vx;
        } else {
          const int cix = t - 25 + xcol;
          float sv = __shfl_sync(0xffffffffu, colsum, cix & 31);
          vx = (t >= 1 && t < 52 && cix >= 0 && cix < 24) ? sv
                                                          : (t == 0 ? e0 : 0.f);
          const int kiy = t - 25 + yrow;
          float sy = __shfl_sync(0xffffffffu, binyreg, kiy & 31);
          vy = (t >= 1 && t < 52 && kiy >= 0 && kiy < 24) ? sy
                                                          : (t == 0 ? e0 : 0.f);
        }
        if (t < 60) {
          bxs[r * 60 + t] = f2tf(vx);
          bys[r * 60 + t] = f2tf(vy);
        }
      }
    } else {
      if (lane == 0) invs[r] = 1.f;
#pragma unroll
      for (int t0 = 0; t0 < 64; t0 += 32) {
        const int t = t0 + lane;
        if (t < 60) {
          bxs[r * 60 + t] = 0u;
          bys[r * 60 + t] = 0u;
        }
      }
    }
  }
  __syncthreads();

  // ---- AV: out[r][d] = sum_m P[r][m] * vT[d][m] ----
  float acc[2][4];
#pragma unroll
  for (int i = 0; i < 2; i++)
#pragma unroll
    for (int j = 0; j < 4; j++) acc[i][j] = 0.f;

  for (int k0 = 0; k0 < 608; k0 += 32) {
    __syncthreads();
    {
      const int d = tid >> 3, m4 = (tid & 7) << 2;
      float4 v = *(const float4*)(g_vT + (size_t)bh * D_ * KTS + (size_t)d * KTS +
                                  k0 + m4);
      *(uint4*)&Vs[d * 36 + m4] =
          make_uint4(f2tf(v.x), f2tf(v.y), f2tf(v.z), f2tf(v.w));
    }
    __syncthreads();
#pragma unroll
    for (int s = 0; s < 4; s++) {
      const int kk = s * 8;
      uint32_t a[4];
      const float* sp = S + (size_t)(warpM * 16 + g) * FA_SSTR + k0 + kk + tg;
      a[0] = f2tf(sp[0]);
      a[1] = f2tf(sp[8 * FA_SSTR]);
      a[2] = f2tf(sp[4]);
      a[3] = f2tf(sp[8 * FA_SSTR + 4]);
#pragma unroll
      for (int nt = 0; nt < 2; nt++) {
        uint32_t b0 = Vs[(warpN * 16 + nt * 8 + g) * 36 + kk + tg];
        uint32_t b1 = Vs[(warpN * 16 + nt * 8 + g) * 36 + kk + tg + 4];
        mma16n8k8(acc[nt], a, b0, b1);
      }
    }
  }

  // ---- value-path bias via mma: bins[64x52] x emb[32x52]^T ----
  const uint32_t* bs = (warpN < 2) ? bxs : bys;
  const uint32_t* es = (warpN < 2) ? exs : eys;
  const int ecol0 = (warpN & 1) * 16;
#pragma unroll
  for (int s = 0; s < 7; s++) {
    const int kk = s * 8;
    uint32_t a[4];
    a[0] = bs[(warpM * 16 + g) * 60 + kk + tg];
    a[1] = bs[(warpM * 16 + g + 8) * 60 + kk + tg];
    a[2] = bs[(warpM * 16 + g) * 60 + kk + tg + 4];
    a[3] = bs[(warpM * 16 + g + 8) * 60 + kk + tg + 4];
#pragma unroll
    for (int nt = 0; nt < 2; nt++) {
      uint32_t b0 = es[(ecol0 + nt * 8 + g) * 60 + kk + tg];
      uint32_t b1 = es[(ecol0 + nt * 8 + g) * 60 + kk + tg + 4];
      mma16n8k8(acc[nt], a, b0, b1);
    }
  }

  // ---- normalize + store ----
  const int b = bh / H_, h = bh % H_;
  const float i0 = invs[warpM * 16 + g], i1 = invs[warpM * 16 + g + 8];
#pragma unroll
  for (int half = 0; half < 2; half++) {
    const int n = row0 + warpM * 16 + g + half * 8;
    if (n >= N_) continue;
    const float inv = half ? i1 : i0;
    float* dst = g_ao + ((size_t)b * N_ + n) * C_ + h * D_ + warpN * 16 + 2 * tg;
    *(float2*)dst = make_float2(acc[0][half * 2] * inv, acc[0][half * 2 + 1] * inv);
    *(float2*)(dst + 8) =
        make_float2(acc[1][half * 2] * inv, acc[1][half * 2 + 1] * inv);
  }
}

// ---------------- launch ----------------
extern "C" void kernel_launch(void* const* d_in, const int* in_sizes, int n_in,
                              void* d_out, int out_size) {
  const float* x = (const float*)d_in[0];
  const float* qkv_w = (const float*)d_in[1];
  const float* proj_w = (const float*)d_in[2];
  const float* qxe = (const float*)d_in[3];
  const float* qye = (const float*)d_in[4];
  const float* vxe = (const float*)d_in[5];
  const float* vye = (const float*)d_in[6];
  float* out = (float*)d_out;

  cudaFuncSetAttribute(fused_attn_kernel,
                       cudaFuncAttributeMaxDynamicSharedMemorySize, FA_SMEM);

  // QKV projection (tf32 tensor cores)
  mma_gemm_kernel<0><<<dim3(18, 73), 256>>>(x, qkv_w, nullptr);

  pxpy_kernel<<<dim3(10, BH_), 256>>>(qxe, qye);

  // fused scores + softmax + bins + AV + bias (tf32 tensor cores)
  fused_attn_kernel<<<dim3(10, BH_), 512, FA_SMEM>>>(vxe, vye);

  // Output projection (tf32 tensor cores)
  mma_gemm_kernel<1><<<dim3(6, 73), 256>>>(nullptr, proj_w, out);
}

// round 7
// speedup vs baseline: 1.0177x; 1.0177x over previous
#include <cuda_runtime.h>
#include <cstdint>

#define B_ 16
#define N_ 577
#define H_ 12
#define D_ 64
#define C_ 768
#define BH_ 192
#define M_ 9232
#define KTS 640       // vT row stride (zero-padded cols 577..639)
#define SST 640       // score row stride
#define SCALE_ 0.125f

// ---------------- device scratch (no cudaMalloc allowed) ----------------
__device__ float g_q[BH_ * N_ * D_];                 // (bh, n, d)
__device__ float g_k[BH_ * N_ * D_];                 // (bh, n, d)
__device__ float g_vT[BH_ * D_ * KTS];               // (bh, d, m) zero-padded
__device__ float g_S[(size_t)(BH_ * N_ + 64) * SST]; // scores, then exp(P)
__device__ float g_pxy[BH_ * N_ * 104];              // px[0:52), py[52:104)
__device__ float g_bins[BH_ * N_ * 104];             // binx[0:52), biny[52:104)
__device__ float g_rowsum[BH_ * N_ + 64];
__device__ float g_ao[M_ * C_];                      // attention out (b*n, c)

// ---------------- tf32 / async helpers (base sm_103 target) ----------------
__device__ __forceinline__ uint32_t f2tf(float f) {
  uint32_t r;
  asm("cvt.rna.tf32.f32 %0, %1;" : "=r"(r) : "f"(f));
  return r;
}
__device__ __forceinline__ void mma16n8k8(float* d, const uint32_t* a,
                                          uint32_t b0, uint32_t b1) {
  asm volatile(
      "mma.sync.aligned.m16n8k8.row.col.f32.tf32.tf32.f32 "
      "{%0,%1,%2,%3}, {%4,%5,%6,%7}, {%8,%9}, {%0,%1,%2,%3};"
      : "+f"(d[0]), "+f"(d[1]), "+f"(d[2]), "+f"(d[3])
      : "r"(a[0]), "r"(a[1]), "r"(a[2]), "r"(a[3]), "r"(b0), "r"(b1));
}
__device__ __forceinline__ uint32_t smem_u32(const void* p) {
  uint32_t a;
  asm("{ .reg .u64 t; cvta.to.shared.u64 t, %1; cvt.u32.u64 %0, t; }"
      : "=r"(a) : "l"(p));
  return a;
}
__device__ __forceinline__ void cp16(uint32_t dst, const void* src, int szbytes) {
  asm volatile("cp.async.cg.shared.global [%0], [%1], 16, %2;" ::"r"(dst),
               "l"(src), "r"(szbytes));
}
__device__ __forceinline__ void cp_commit() {
  asm volatile("cp.async.commit_group;" ::: "memory");
}
template <int NN>
__device__ __forceinline__ void cp_wait() {
  asm volatile("cp.async.wait_group %0;" ::"n"(NN) : "memory");
}

// ======== pipelined tf32 mma.sync GEMM: C[m,c] = sum_k A[m,k]*W[c,k] ========
// 128x128 CTA tile, 256 threads, BK=32, 2-stage cp.async double buffer.
// MODE 0: A = x, scatter-store q/k natural + vT transposed
// MODE 1: A = g_ao, row-major store into out
#define MG_SMEM (4 * 128 * 36 * 4)  // 73728 B: A[2][128][36] + B[2][128][36]

template <int MODE>
__global__ __launch_bounds__(256)
void mma_gemm_kernel(const float* __restrict__ Ain, const float* __restrict__ W,
                     float* __restrict__ out) {
  extern __shared__ float smf[];
  const uint32_t smb = smem_u32(smf);
  const float* A = (MODE == 0) ? Ain : (const float*)g_ao;
  const int row0 = blockIdx.y * 128, col0 = blockIdx.x * 128;
  const int tid = threadIdx.x, lane = tid & 31, wid = tid >> 5;
  const int warpM = wid & 3, warpN = wid >> 2;
  const int g = lane >> 2, tg = lane & 3;

  float acc[16][4];
#pragma unroll
  for (int i = 0; i < 16; i++)
#pragma unroll
    for (int j = 0; j < 4; j++) acc[i][j] = 0.f;

  const int lr = tid >> 1;           // 0..127
  const int lkq = (tid & 1) * 16;    // 0 / 16
  const int asz = ((row0 + lr) < M_) ? 16 : 0;
  const float* ap = A + (size_t)(row0 + lr) * C_ + lkq;
  const float* bp = W + (size_t)(col0 + lr) * C_ + lkq;
  const uint32_t adst = smb + (uint32_t)(lr * 36 + lkq) * 4;
  const uint32_t bdst = adst + 2 * 128 * 36 * 4;

  // prefetch tile 0
#pragma unroll
  for (int i = 0; i < 4; i++) {
    cp16(adst + i * 16, ap + i * 4, asz);
    cp16(bdst + i * 16, bp + i * 4, 16);
  }
  cp_commit();

  const int NT = C_ / 32;  // 24
  for (int kt = 0; kt < NT; kt++) {
    const int buf = kt & 1;
    if (kt < NT - 1) {
      const int nb = (kt + 1) & 1;
      const uint32_t ad = adst + nb * 128 * 36 * 4;
      const uint32_t bd = bdst + nb * 128 * 36 * 4;
      const float* an = ap + (kt + 1) * 32;
      const float* bn = bp + (kt + 1) * 32;
#pragma unroll
      for (int i = 0; i < 4; i++) {
        cp16(ad + i * 16, an + i * 4, asz);
        cp16(bd + i * 16, bn + i * 4, 16);
      }
      cp_commit();
      cp_wait<1>();
    } else {
      cp_wait<0>();
    }
    __syncthreads();
    const float* Ab = smf + buf * 128 * 36;
    const float* Bb = smf + 2 * 128 * 36 + buf * 128 * 36;
#pragma unroll
    for (int s = 0; s < 4; s++) {
      const int kk = s * 8;
      uint32_t a[2][4];
#pragma unroll
      for (int mt = 0; mt < 2; mt++) {
        const int r = warpM * 32 + mt * 16;
        a[mt][0] = f2tf(Ab[(r + g) * 36 + kk + tg]);
        a[mt][1] = f2tf(Ab[(r + g + 8) * 36 + kk + tg]);
        a[mt][2] = f2tf(Ab[(r + g) * 36 + kk + tg + 4]);
        a[mt][3] = f2tf(Ab[(r + g + 8) * 36 + kk + tg + 4]);
      }
#pragma unroll
      for (int nt = 0; nt < 8; nt++) {
        const int c = warpN * 64 + nt * 8;
        uint32_t b0 = f2tf(Bb[(c + g) * 36 + kk + tg]);
        uint32_t b1 = f2tf(Bb[(c + g) * 36 + kk + tg + 4]);
        mma16n8k8(acc[nt], a[0], b0, b1);
        mma16n8k8(acc[8 + nt], a[1], b0, b1);
      }
    }
    __syncthreads();
  }

  if (MODE == 1) {
#pragma unroll
    for (int mt = 0; mt < 2; mt++)
#pragma unroll
      for (int half = 0; half < 2; half++) {
        const int m = row0 + warpM * 32 + mt * 16 + g + half * 8;
        if (m >= M_) continue;
        float* dst = out + (size_t)m * C_ + col0 + warpN * 64 + 2 * tg;
#pragma unroll
        for (int nt = 0; nt < 8; nt++)
          *(float2*)(dst + nt * 8) = make_float2(acc[mt * 8 + nt][half * 2],
                                                 acc[mt * 8 + nt][half * 2 + 1]);
      }
  } else {
    const int cg = col0 + warpN * 64;   // multiple of 64 -> one head per warp
    const int which = cg / C_;          // 0=q 1=k 2=v
    const int h = (cg % C_) / D_;
#pragma unroll
    for (int mt = 0; mt < 2; mt++)
#pragma unroll
      for (int half = 0; half < 2; half++) {
        const int m = row0 + warpM * 32 + mt * 16 + g + half * 8;
        if (m >= M_) continue;
        const int b = m / N_, n = m % N_;
        const int bh = b * H_ + h;
        if (which == 2) {
          const size_t base = (size_t)bh * D_ * KTS + n;
          const int d0 = 2 * tg;
#pragma unroll
          for (int nt = 0; nt < 8; nt++) {
            g_vT[base + (size_t)(d0 + nt * 8) * KTS] = acc[mt * 8 + nt][half * 2];
            g_vT[base + (size_t)(d0 + nt * 8 + 1) * KTS] =
                acc[mt * 8 + nt][half * 2 + 1];
          }
        } else {
          float* dst = (which == 0 ? g_q : g_k) + ((size_t)bh * N_ + n) * D_ + 2 * tg;
#pragma unroll
          for (int nt = 0; nt < 8; nt++)
            *(float2*)(dst + nt * 8) =
                make_float2(acc[mt * 8 + nt][half * 2],
                            acc[mt * 8 + nt][half * 2 + 1]);
        }
      }
  }
}

// ---------------- px/py projection ----------------
__global__ __launch_bounds__(256)
void pxpy_kernel(const float* __restrict__ qxe, const float* __restrict__ qye) {
  __shared__ float qs[64][65];
  __shared__ float ex[50][33];
  __shared__ float ey[50][33];
  const int bh = blockIdx.y;
  const int row0 = blockIdx.x * 64;
  const int tid = threadIdx.x;
  for (int f = tid; f < 64 * 16; f += 256) {
    int r = f >> 4, c4 = (f & 15) << 2;
    int n = row0 + r;
    float4 v = (n < N_) ? *(const float4*)(g_q + ((size_t)bh * N_ + n) * D_ + c4)
                        : make_float4(0.f, 0.f, 0.f, 0.f);
    qs[r][c4 + 0] = v.x; qs[r][c4 + 1] = v.y;
    qs[r][c4 + 2] = v.z; qs[r][c4 + 3] = v.w;
  }
  for (int f = tid; f < 1600; f += 256) {
    ex[f >> 5][f & 31] = qxe[f];
    ey[f >> 5][f & 31] = qye[f];
  }
  __syncthreads();
  for (int idx = tid; idx < 64 * 50; idx += 256) {
    int r = idx / 50, t = idx % 50;
    float ax = 0.f, ay = 0.f;
#pragma unroll
    for (int d = 0; d < 32; d++) {
      ax += qs[r][d] * ex[t][d];
      ay += qs[r][32 + d] * ey[t][d];
    }
    int n = row0 + r;
    if (n < N_) {
      float* p = g_pxy + ((size_t)bh * N_ + n) * 104;
      p[t] = ax;
      p[52 + t] = ay;
    }
  }
}

// ---------------- scores via mma: S[bh,n,m] = q·k ----------------
__global__ __launch_bounds__(256)
void scores_mma_kernel() {
  __shared__ uint32_t As[128][36];
  __shared__ uint32_t Bs[128][36];
  const int bh = blockIdx.z;
  const int row0 = blockIdx.y * 128, col0 = blockIdx.x * 128;
  const int tid = threadIdx.x, lane = tid & 31, wid = tid >> 5;
  const int warpM = wid & 3, warpN = wid >> 2;
  const int g = lane >> 2, tg = lane & 3;

  float acc[16][4];
#pragma unroll
  for (int i = 0; i < 16; i++)
#pragma unroll
    for (int j = 0; j < 4; j++) acc[i][j] = 0.f;

  const int lr = tid >> 1;
  const int lkq = (tid & 1) * 16;
  const bool aval = (row0 + lr) < N_;
  const bool bval = (col0 + lr) < N_;
  const float* ap = g_q + ((size_t)bh * N_ + row0 + lr) * D_ + lkq;
  const float* bp = g_k + ((size_t)bh * N_ + col0 + lr) * D_ + lkq;

  for (int k0 = 0; k0 < 64; k0 += 32) {
    __syncthreads();
#pragma unroll
    for (int i = 0; i < 4; i++) {
      float4 va = aval ? *(const float4*)(ap + k0 + i * 4)
                       : make_float4(0.f, 0.f, 0.f, 0.f);
      float4 vb = bval ? *(const float4*)(bp + k0 + i * 4)
                       : make_float4(0.f, 0.f, 0.f, 0.f);
      *(uint4*)&As[lr][lkq + i * 4] =
          make_uint4(f2tf(va.x), f2tf(va.y), f2tf(va.z), f2tf(va.w));
      *(uint4*)&Bs[lr][lkq + i * 4] =
          make_uint4(f2tf(vb.x), f2tf(vb.y), f2tf(vb.z), f2tf(vb.w));
    }
    __syncthreads();
#pragma unroll
    for (int s = 0; s < 4; s++) {
      const int kk = s * 8;
      uint32_t a[2][4];
#pragma unroll
      for (int mt = 0; mt < 2; mt++) {
        const int r = warpM * 32 + mt * 16;
        a[mt][0] = As[r + g][kk + tg];
        a[mt][1] = As[r + g + 8][kk + tg];
        a[mt][2] = As[r + g][kk + tg + 4];
        a[mt][3] = As[r + g + 8][kk + tg + 4];
      }
#pragma unroll
      for (int nt = 0; nt < 8; nt++) {
        const int c = warpN * 64 + nt * 8;
        uint32_t b0 = Bs[c + g][kk + tg];
        uint32_t b1 = Bs[c + g][kk + tg + 4];
        mma16n8k8(acc[nt], a[0], b0, b1);
        mma16n8k8(acc[8 + nt], a[1], b0, b1);
      }
    }
  }

#pragma unroll
  for (int mt = 0; mt < 2; mt++)
#pragma unroll
    for (int half = 0; half < 2; half++) {
      const int n = row0 + warpM * 32 + mt * 16 + g + half * 8;
      if (n >= N_) continue;
      float* dst = g_S + ((size_t)bh * N_ + n) * SST + col0 + warpN * 64 + 2 * tg;
#pragma unroll
      for (int nt = 0; nt < 8; nt++)
        *(float2*)(dst + nt * 8) = make_float2(acc[mt * 8 + nt][half * 2],
                                               acc[mt * 8 + nt][half * 2 + 1]);
    }
}

// ---------------- softmax + bias + analytic binning ----------------
__global__ __launch_bounds__(256)
void softmax_kernel() {
  __shared__ float st[8][64];
  const int w = threadIdx.x >> 5, lane = threadIdx.x & 31;
  const int row = blockIdx.x * 8 + w;
  if (row >= BH_ * N_) return;
  const int n = row % N_;
  float* Srow = g_S + (size_t)row * SST;
  const float* pxy = g_pxy + (size_t)row * 104;
  const bool cls = (n == 0);
  const int xcol = cls ? 0 : (n - 1) % 24;
  const int yrow = cls ? 0 : (n - 1) / 24;

  float pxl = 0.f, pyl = 0.f;
  if (lane < 24) {
    pxl = cls ? pxy[0] : pxy[25 + lane - xcol];
    pyl = cls ? pxy[52] : pxy[52 + 25 + lane - yrow];
  }
  const float l0 = (Srow[0] + pxy[0] + pxy[52]) * SCALE_;
  float mx = l0;
  float lg[24];
#pragma unroll
  for (int k = 0; k < 24; k++) {
    float pyk = __shfl_sync(0xffffffffu, pyl, k);
    float s = -1e30f;
    if (lane < 24) s = (Srow[1 + 24 * k + lane] + pxl + pyk) * SCALE_;
    lg[k] = s;
    mx = fmaxf(mx, s);
  }
#pragma unroll
  for (int o = 16; o; o >>= 1) mx = fmaxf(mx, __shfl_xor_sync(0xffffffffu, mx, o));

  float colsum = 0.f, total = 0.f, binyreg = 0.f;
  const float e0 = __expf(l0 - mx);
#pragma unroll
  for (int k = 0; k < 24; k++) {
    float e = 0.f;
    if (lane < 24) {
      e = __expf(lg[k] - mx);
      Srow[1 + 24 * k + lane] = e;
    }
    colsum += e;
    float rs = e;
#pragma unroll
    for (int o = 16; o; o >>= 1) rs += __shfl_xor_sync(0xffffffffu, rs, o);
    total += rs;
    if (lane == k) binyreg = rs;
  }
  if (lane == 0) Srow[0] = e0;
  Srow[577 + lane] = 0.f;  // zero-pad cols 577..608 for the AV mma
  total += e0;
  if (lane == 0) g_rowsum[row] = total;

  st[w][lane] = colsum;
  st[w][32 + lane] = binyreg;
  __syncwarp();
  float* brow = g_bins + (size_t)row * 104;
  for (int t = lane; t < 104; t += 32) {
    float v = 0.f;
    if (cls) {
      if (t == 0 || t == 52) v = total;
    } else if (t == 0 || t == 52) {
      v = e0;
    } else if (t < 52) {
      int c = t - 25 + xcol;
      if (c >= 0 && c < 24) v = st[w][c];
    } else {
      int k = (t - 52) - 25 + yrow;
      if (k >= 0 && k < 24) v = st[w][32 + k];
    }
    brow[t] = v;
  }
}

// ---------------- AV via mma + bias-mma + normalize ----------------
#define AV_SMEM 77312
__global__ __launch_bounds__(256)
void av_mma_kernel(const float* __restrict__ vxe, const float* __restrict__ vye) {
  extern __shared__ uint32_t dsm[];
  uint32_t(*As)[36] = (uint32_t(*)[36])dsm;              // P tile 128x32
  uint32_t(*Bs)[36] = (uint32_t(*)[36])(dsm + 128 * 36); // vT tile 64x32
  const int bh = blockIdx.y, row0 = blockIdx.x * 128;
  const int tid = threadIdx.x, lane = tid & 31, wid = tid >> 5;
  const int g = lane >> 2, tg = lane & 3;

  float acc[8][4];
#pragma unroll
  for (int i = 0; i < 8; i++)
#pragma unroll
    for (int j = 0; j < 4; j++) acc[i][j] = 0.f;

  const int lr = tid >> 1, lk = (tid & 1) * 16;
  const float* ap = g_S + ((size_t)bh * N_ + row0 + lr) * SST + lk;
  const int vr = tid >> 2, vc = (tid & 3) * 8;
  const float* vp = g_vT + (size_t)bh * D_ * KTS + (size_t)vr * KTS + vc;
  const int wr = wid * 16;

  for (int k0 = 0; k0 < 608; k0 += 32) {
    __syncthreads();
#pragma unroll
    for (int i = 0; i < 4; i++) {
      float4 va = *(const float4*)(ap + k0 + i * 4);
      *(uint4*)&As[lr][lk + i * 4] =
          make_uint4(f2tf(va.x), f2tf(va.y), f2tf(va.z), f2tf(va.w));
    }
#pragma unroll
    for (int i = 0; i < 2; i++) {
      float4 vb = *(const float4*)(vp + k0 + i * 4);
      *(uint4*)&Bs[vr][vc + i * 4] =
          make_uint4(f2tf(vb.x), f2tf(vb.y), f2tf(vb.z), f2tf(vb.w));
    }
    __syncthreads();
#pragma unroll
    for (int s = 0; s < 4; s++) {
      const int kk = s * 8;
      uint32_t a[4];
      a[0] = As[wr + g][kk + tg];
      a[1] = As[wr + g + 8][kk + tg];
      a[2] = As[wr + g][kk + tg + 4];
      a[3] = As[wr + g + 8][kk + tg + 4];
#pragma unroll
      for (int nt = 0; nt < 8; nt++) {
        uint32_t b0 = Bs[nt * 8 + g][kk + tg];
        uint32_t b1 = Bs[nt * 8 + g][kk + tg + 4];
        mma16n8k8(acc[nt], a, b0, b1);
      }
    }
  }
  __syncthreads();

  // ---- bias phase: bins (128x52) x emb^T (32x52) accumulated via mma ----
  uint32_t* bxs = dsm;                         // [128][60]
  uint32_t* bys = dsm + 128 * 60;              // [128][60]
  uint32_t* exs = dsm + 2 * 128 * 60;          // [32][60]
  uint32_t* eys = dsm + 2 * 128 * 60 + 32 * 60;
  float* invs = (float*)(dsm + 2 * 128 * 60 + 2 * 32 * 60);  // [128]

  for (int f = tid; f < 128 * 60; f += 256) {
    int r = f / 60, t = f % 60;
    int n = row0 + r;
    float vx = 0.f, vy = 0.f;
    if (t < 52 && n < N_) {
      const float* p = g_bins + ((size_t)bh * N_ + n) * 104;
      vx = p[t];
      vy = p[52 + t];
    }
    bxs[r * 60 + t] = f2tf(vx);
    bys[r * 60 + t] = f2tf(vy);
  }
  for (int f = tid; f < 32 * 60; f += 256) {
    int c = f / 60, t = f % 60;
    float ax = 0.f, ay = 0.f;
    if (t < 50) {
      ax = vxe[t * 32 + c];
      ay = vye[t * 32 + c];
    }
    exs[f] = f2tf(ax);
    eys[f] = f2tf(ay);
  }
  for (int f = tid; f < 128; f += 256) {
    int n = row0 + f;
    invs[f] = (n < N_) ? 1.f / g_rowsum[(size_t)bh * N_ + n] : 1.f;
  }
  __syncthreads();

#pragma unroll
  for (int s = 0; s < 7; s++) {
    const int kk = s * 8;
    uint32_t ax[4], ay[4];
    ax[0] = bxs[(wr + g) * 60 + kk + tg];
    ax[1] = bxs[(wr + g + 8) * 60 + kk + tg];
    ax[2] = bxs[(wr + g) * 60 + kk + tg + 4];
    ax[3] = bxs[(wr + g + 8) * 60 + kk + tg + 4];
    ay[0] = bys[(wr + g) * 60 + kk + tg];
    ay[1] = bys[(wr + g + 8) * 60 + kk + tg];
    ay[2] = bys[(wr + g) * 60 + kk + tg + 4];
    ay[3] = bys[(wr + g + 8) * 60 + kk + tg + 4];
#pragma unroll
    for (int nt = 0; nt < 4; nt++) {
      uint32_t b0 = exs[(nt * 8 + g) * 60 + kk + tg];
      uint32_t b1 = exs[(nt * 8 + g) * 60 + kk + tg + 4];
      mma16n8k8(acc[nt], ax, b0, b1);
    }
#pragma unroll
    for (int nt = 0; nt < 4; nt++) {
      uint32_t b0 = eys[(nt * 8 + g) * 60 + kk + tg];
      uint32_t b1 = eys[(nt * 8 + g) * 60 + kk + tg + 4];
      mma16n8k8(acc[4 + nt], ay, b0, b1);
    }
  }

  // ---- normalize + store ----
  const float i0 = invs[wr + g], i1 = invs[wr + g + 8];
  const int b = bh / H_, h = bh % H_;
#pragma unroll
  for (int half = 0; half < 2; half++) {
    const int n = row0 + wr + g + half * 8;
    if (n >= N_) continue;
    const float inv = half ? i1 : i0;
    float* dst = g_ao + ((size_t)b * N_ + n) * C_ + h * D_ + 2 * tg;
#pragma unroll
    for (int nt = 0; nt < 8; nt++)
      *(float2*)(dst + nt * 8) = make_float2(acc[nt][half * 2] * inv,
                                             acc[nt][half * 2 + 1] * inv);
  }
}

// ---------------- launch ----------------
extern "C" void kernel_launch(void* const* d_in, const int* in_sizes, int n_in,
                              void* d_out, int out_size) {
  const float* x = (const float*)d_in[0];
  const float* qkv_w = (const float*)d_in[1];
  const float* proj_w = (const float*)d_in[2];
  const float* qxe = (const float*)d_in[3];
  const float* qye = (const float*)d_in[4];
  const float* vxe = (const float*)d_in[5];
  const float* vye = (const float*)d_in[6];
  float* out = (float*)d_out;

  cudaFuncSetAttribute(mma_gemm_kernel<0>,
                       cudaFuncAttributeMaxDynamicSharedMemorySize, MG_SMEM);
  cudaFuncSetAttribute(mma_gemm_kernel<1>,
                       cudaFuncAttributeMaxDynamicSharedMemorySize, MG_SMEM);
  cudaFuncSetAttribute(av_mma_kernel, cudaFuncAttributeMaxDynamicSharedMemorySize,
                       AV_SMEM);

  // QKV projection (pipelined tf32 tensor cores)
  mma_gemm_kernel<0><<<dim3(18, 73), 256, MG_SMEM>>>(x, qkv_w, nullptr);

  pxpy_kernel<<<dim3(10, BH_), 256>>>(qxe, qye);

  // scores (tf32 tensor cores)
  scores_mma_kernel<<<dim3(5, 5, BH_), 256>>>();

  softmax_kernel<<<(BH_ * N_ + 7) / 8, 256>>>();

  // AV + bias (tf32 tensor cores)
  av_mma_kernel<<<dim3(5, BH_), 256, AV_SMEM>>>(vxe, vye);

  // Output projection (pipelined tf32 tensor cores)
  mma_gemm_kernel<1><<<dim3(6, 73), 256, MG_SMEM>>>(nullptr, proj_w, out);
}